// round 2
// baseline (speedup 1.0000x reference)
#include <cuda_runtime.h>
#include <math.h>

#define N_ATOMS 100000
#define M_NBR   12
#define F_DIM   64
#define C_DIM   128              // 2F
#define KW      192              // 2F + NBR
#define P_ROWS  (N_ATOMS * M_NBR)  // 1200000
#define BN_EPS  1e-5f

// ---------------- scratch (device globals: allocation-free) ----------------
__device__ __align__(256) float g_S [N_ATOMS * C_DIM];              // W_self·a + b
__device__ __align__(256) float g_P [N_ATOMS * C_DIM];              // W_nbr·a
__device__ __align__(256) float g_Z [(size_t)P_ROWS * C_DIM];       // gated pre-BN (614MB)
__device__ __align__(256) float g_NS[N_ATOMS * F_DIM];              // nbr_sumed pre-BN2
__device__ float g_stats1[2 * C_DIM];   // [sum(128) | sumsq(128)]
__device__ float g_stats2[2 * F_DIM];   // [sum(64)  | sumsq(64)]
__device__ float g_aff1 [2 * C_DIM];    // [scale | shift]
__device__ float g_aff2 [2 * F_DIM];

__device__ __forceinline__ float softplus_f(float x) {
    return fmaxf(x, 0.f) + log1pf(__expf(-fabsf(x)));
}

// ---------------- K0: zero the stat accumulators ----------------
__global__ void k0_zero() {
    int t = threadIdx.x;
    if (t < 2 * C_DIM) g_stats1[t] = 0.f;
    if (t < 2 * F_DIM) g_stats2[t] = 0.f;
}

// ---------------- K1: S[n,c] = b[c] + W_self·a[n] ; P[n,c] = W_nbr·a[n] ----
// 32 rows x 128 cols per block, 128 threads, 4x8 register tile, two phases.
__global__ __launch_bounds__(128, 4) void k1_selfnbr(
        const float* __restrict__ atom, const float* __restrict__ W,
        const float* __restrict__ b) {
    __shared__ __align__(16) float sW[64 * 128];
    __shared__ __align__(16) float sA[64 * 36];
    const int tid = threadIdx.x;
    const int n0  = blockIdx.x * 32;

    for (int i = tid; i < 32 * 64; i += 128) {
        int r = i >> 6, k = i & 63;
        sA[k * 36 + r] = atom[(n0 + r) * 64 + k];
    }
    const int rg = tid >> 4, cg = tid & 15;
    const int r0 = rg * 4,  c0 = cg * 8;

    for (int half = 0; half < 2; ++half) {
        __syncthreads();
        for (int i = tid; i < 64 * 128; i += 128) {
            int c = i >> 6, k = i & 63;
            sW[k * 128 + c] = W[c * KW + half * 64 + k];
        }
        __syncthreads();

        float acc[4][8];
        #pragma unroll
        for (int r = 0; r < 4; r++)
            #pragma unroll
            for (int c = 0; c < 8; c++)
                acc[r][c] = (half == 0) ? b[c0 + c] : 0.f;

        #pragma unroll 8
        for (int k = 0; k < 64; ++k) {
            float4 av = *(const float4*)&sA[k * 36 + r0];
            float4 w0 = *(const float4*)&sW[k * 128 + c0];
            float4 w1 = *(const float4*)&sW[k * 128 + c0 + 4];
            float a_[4] = {av.x, av.y, av.z, av.w};
            float w_[8] = {w0.x, w0.y, w0.z, w0.w, w1.x, w1.y, w1.z, w1.w};
            #pragma unroll
            for (int r = 0; r < 4; r++)
                #pragma unroll
                for (int c = 0; c < 8; c++)
                    acc[r][c] = fmaf(a_[r], w_[c], acc[r][c]);
        }

        float* dst = (half == 0) ? g_S : g_P;
        #pragma unroll
        for (int r = 0; r < 4; r++) {
            int n = n0 + r0 + r;
            float4 q0 = make_float4(acc[r][0], acc[r][1], acc[r][2], acc[r][3]);
            float4 q1 = make_float4(acc[r][4], acc[r][5], acc[r][6], acc[r][7]);
            *(float4*)&dst[n * C_DIM + c0]     = q0;
            *(float4*)&dst[n * C_DIM + c0 + 4] = q1;
        }
    }
}

// ---------------- K2: Z[p,c] = S[n,c] + P[idx[p],c] + W_edge·nbr[p] + stats1
__global__ __launch_bounds__(128, 4) void k2_edge(
        const float* __restrict__ nbr, const int* __restrict__ idx,
        const float* __restrict__ W) {
    __shared__ __align__(16) float sW[64 * 128];
    __shared__ __align__(16) float sE[64 * 36];
    __shared__ float sSum[128], sSq[128];
    const int tid = threadIdx.x;
    if (tid < 128) { sSum[tid] = 0.f; sSq[tid] = 0.f; }
    for (int i = tid; i < 64 * 128; i += 128) {
        int c = i >> 6, k = i & 63;
        sW[k * 128 + c] = W[c * KW + 128 + k];
    }
    const int rg = tid >> 4, cg = tid & 15;
    const int r0 = rg * 4,  c0 = cg * 8;

    float lsum[8], lsq[8];
    #pragma unroll
    for (int c = 0; c < 8; c++) { lsum[c] = 0.f; lsq[c] = 0.f; }

    const int ntiles = P_ROWS / 32;  // 37500
    for (int tile = blockIdx.x; tile < ntiles; tile += gridDim.x) {
        const int p0 = tile * 32;
        __syncthreads();
        for (int i = tid; i < 32 * 64; i += 128) {
            int r = i >> 6, k = i & 63;
            sE[k * 36 + r] = nbr[(size_t)(p0 + r) * 64 + k];
        }
        __syncthreads();

        float acc[4][8];
        #pragma unroll
        for (int r = 0; r < 4; r++)
            #pragma unroll
            for (int c = 0; c < 8; c++) acc[r][c] = 0.f;

        #pragma unroll 8
        for (int k = 0; k < 64; ++k) {
            float4 av = *(const float4*)&sE[k * 36 + r0];
            float4 w0 = *(const float4*)&sW[k * 128 + c0];
            float4 w1 = *(const float4*)&sW[k * 128 + c0 + 4];
            float a_[4] = {av.x, av.y, av.z, av.w};
            float w_[8] = {w0.x, w0.y, w0.z, w0.w, w1.x, w1.y, w1.z, w1.w};
            #pragma unroll
            for (int r = 0; r < 4; r++)
                #pragma unroll
                for (int c = 0; c < 8; c++)
                    acc[r][c] = fmaf(a_[r], w_[c], acc[r][c]);
        }

        #pragma unroll
        for (int r = 0; r < 4; r++) {
            const int p = p0 + r0 + r;
            const int n = p / 12;
            const int j = __ldg(&idx[p]);
            float4 s0 = *(const float4*)&g_S[n * C_DIM + c0];
            float4 s1 = *(const float4*)&g_S[n * C_DIM + c0 + 4];
            float4 pv0 = *(const float4*)&g_P[j * C_DIM + c0];
            float4 pv1 = *(const float4*)&g_P[j * C_DIM + c0 + 4];
            float z[8];
            z[0] = acc[r][0] + s0.x + pv0.x;  z[1] = acc[r][1] + s0.y + pv0.y;
            z[2] = acc[r][2] + s0.z + pv0.z;  z[3] = acc[r][3] + s0.w + pv0.w;
            z[4] = acc[r][4] + s1.x + pv1.x;  z[5] = acc[r][5] + s1.y + pv1.y;
            z[6] = acc[r][6] + s1.z + pv1.z;  z[7] = acc[r][7] + s1.w + pv1.w;
            #pragma unroll
            for (int c = 0; c < 8; c++) {
                lsum[c] += z[c];
                lsq[c]  = fmaf(z[c], z[c], lsq[c]);
            }
            float4 q0 = make_float4(z[0], z[1], z[2], z[3]);
            float4 q1 = make_float4(z[4], z[5], z[6], z[7]);
            __stcs((float4*)&g_Z[(size_t)p * C_DIM + c0],     q0);
            __stcs((float4*)&g_Z[(size_t)p * C_DIM + c0 + 4], q1);
        }
    }

    #pragma unroll
    for (int c = 0; c < 8; c++) {
        atomicAdd(&sSum[c0 + c], lsum[c]);
        atomicAdd(&sSq[c0 + c],  lsq[c]);
    }
    __syncthreads();
    if (tid < 128) {
        atomicAdd(&g_stats1[tid],        sSum[tid]);
        atomicAdd(&g_stats1[128 + tid],  sSq[tid]);
    }
}

// ---------------- K3: BN1 affine coefficients ----------------
__global__ void k3_aff1(const float* __restrict__ gamma1,
                        const float* __restrict__ beta1) {
    int c = threadIdx.x;  // 128
    float inv  = 1.f / (float)P_ROWS;
    float mean = g_stats1[c] * inv;
    float var  = g_stats1[128 + c] * inv - mean * mean;
    float sc   = gamma1[c] * rsqrtf(var + BN_EPS);
    g_aff1[c]        = sc;
    g_aff1[128 + c]  = beta1[c] - mean * sc;
}

// ---------------- K4: BN1 apply + gate + sum over M + stats2 ----------------
__global__ __launch_bounds__(256) void k4_reduce(const float* __restrict__ bw) {
    __shared__ float sSum[64], sSq[64];
    const int tid = threadIdx.x;
    if (tid < 64) { sSum[tid] = 0.f; sSq[tid] = 0.f; }
    __syncthreads();
    const int f  = tid & 63;
    const int al = tid >> 6;  // 0..3
    const float sc1 = g_aff1[f],      sh1 = g_aff1[128 + f];
    const float sc2 = g_aff1[64 + f], sh2 = g_aff1[192 + f];
    float lsum = 0.f, lsq = 0.f;

    for (int n = blockIdx.x * 4 + al; n < N_ATOMS; n += gridDim.x * 4) {
        float acc = 0.f;
        #pragma unroll
        for (int m = 0; m < 12; m++) {
            size_t base = (size_t)(n * 12 + m) * C_DIM;
            float z1 = fmaf(g_Z[base + f],      sc1, sh1);
            float z2 = fmaf(g_Z[base + 64 + f], sc2, sh2);
            float w  = bw[n * 12 + m];
            float filt = w / (1.f + __expf(-z1));
            float core = w * softplus_f(z2);
            acc = fmaf(filt, core, acc);
        }
        g_NS[n * 64 + f] = acc;
        lsum += acc;
        lsq  = fmaf(acc, acc, lsq);
    }
    atomicAdd(&sSum[f], lsum);
    atomicAdd(&sSq[f],  lsq);
    __syncthreads();
    if (tid < 64) {
        atomicAdd(&g_stats2[tid],      sSum[tid]);
        atomicAdd(&g_stats2[64 + tid], sSq[tid]);
    }
}

// ---------------- K5: BN2 affine coefficients ----------------
__global__ void k5_aff2(const float* __restrict__ gamma2,
                        const float* __restrict__ beta2) {
    int f = threadIdx.x;  // 64
    float inv  = 1.f / (float)N_ATOMS;
    float mean = g_stats2[f] * inv;
    float var  = g_stats2[64 + f] * inv - mean * mean;
    float sc   = gamma2[f] * rsqrtf(var + BN_EPS);
    g_aff2[f]       = sc;
    g_aff2[64 + f]  = beta2[f] - mean * sc;
}

// ---------------- K6: out = softplus(atom + BN2(NS)) ----------------
__global__ void k6_out(const float* __restrict__ atom, float* __restrict__ out) {
    int i = blockIdx.x * blockDim.x + threadIdx.x;
    if (i < N_ATOMS * F_DIM) {
        int f = i & 63;
        float x = atom[i] + fmaf(g_NS[i], g_aff2[f], g_aff2[64 + f]);
        out[i] = softplus_f(x);
    }
}

// ---------------- launch ----------------
extern "C" void kernel_launch(void* const* d_in, const int* in_sizes, int n_in,
                              void* d_out, int out_size) {
    const float* atom   = (const float*)d_in[0];
    const float* nbr    = (const float*)d_in[1];
    const float* bw     = (const float*)d_in[2];
    const int*   idx    = (const int*)  d_in[3];
    const float* W      = (const float*)d_in[4];
    const float* b      = (const float*)d_in[5];
    const float* gamma1 = (const float*)d_in[6];
    const float* beta1  = (const float*)d_in[7];
    const float* gamma2 = (const float*)d_in[8];
    const float* beta2  = (const float*)d_in[9];
    float* out = (float*)d_out;

    k0_zero<<<1, 256>>>();
    k1_selfnbr<<<N_ATOMS / 32, 128>>>(atom, W, b);
    k2_edge<<<592, 128>>>(nbr, idx, W);
    k3_aff1<<<1, 128>>>(gamma1, beta1);
    k4_reduce<<<592, 256>>>(bw);
    k5_aff2<<<1, 64>>>(gamma2, beta2);
    k6_out<<<(N_ATOMS * F_DIM + 255) / 256, 256>>>(atom, out);
}

// round 3
// speedup vs baseline: 1.1269x; 1.1269x over previous
#include <cuda_runtime.h>
#include <math.h>

#define N_ATOMS 100000
#define M_NBR   12
#define F_DIM   64
#define C_DIM   128              // 2F
#define KW      192              // 2F + NBR
#define P_ROWS  (N_ATOMS * M_NBR)  // 1200000
#define BN_EPS  1e-5f

typedef unsigned long long u64;

// ---------------- scratch (device globals: allocation-free) ----------------
__device__ __align__(256) float g_S [N_ATOMS * C_DIM];              // W_self·a + b
__device__ __align__(256) float g_P [N_ATOMS * C_DIM];              // W_nbr·a
__device__ __align__(256) float g_Z [(size_t)P_ROWS * C_DIM];       // gated pre-BN (614MB)
__device__ __align__(256) float g_NS[N_ATOMS * F_DIM];              // nbr_sumed pre-BN2
__device__ float g_stats1[2 * C_DIM];   // [sum(128) | sumsq(128)]
__device__ float g_stats2[2 * F_DIM];   // [sum(64)  | sumsq(64)]
__device__ float g_aff1 [2 * C_DIM];    // [scale | shift]
__device__ float g_aff2 [2 * F_DIM];

// ---------------- packed f32x2 helpers (Blackwell FFMA2 path) -------------
__device__ __forceinline__ u64 pack2(float lo, float hi) {
    u64 r;
    asm("mov.b64 %0, {%1, %2};" : "=l"(r) : "r"(__float_as_uint(lo)), "r"(__float_as_uint(hi)));
    return r;
}
__device__ __forceinline__ u64 dup2(float a) {
    u64 r;
    unsigned int u = __float_as_uint(a);
    asm("mov.b64 %0, {%1, %1};" : "=l"(r) : "r"(u));
    return r;
}
__device__ __forceinline__ void unpack2(u64 v, float& lo, float& hi) {
    unsigned int a, b;
    asm("mov.b64 {%0, %1}, %2;" : "=r"(a), "=r"(b) : "l"(v));
    lo = __uint_as_float(a); hi = __uint_as_float(b);
}
__device__ __forceinline__ u64 ffma2(u64 a, u64 b, u64 c) {
    u64 d;
    asm("fma.rn.f32x2 %0, %1, %2, %3;" : "=l"(d) : "l"(a), "l"(b), "l"(c));
    return d;
}
__device__ __forceinline__ u64 add2(u64 a, u64 b) {
    u64 d;
    asm("add.rn.f32x2 %0, %1, %2;" : "=l"(d) : "l"(a), "l"(b));
    return d;
}

__device__ __forceinline__ float softplus_fast(float x) {
    return fmaxf(x, 0.f) + __logf(1.f + __expf(-fabsf(x)));
}

// ---------------- K0: zero the stat accumulators ----------------
__global__ void k0_zero() {
    int t = threadIdx.x;
    if (t < 2 * C_DIM) g_stats1[t] = 0.f;
    if (t < 2 * F_DIM) g_stats2[t] = 0.f;
}

// ---------------- K1: S[n,c] = b[c] + W_self·a[n] ; P[n,c] = W_nbr·a[n] ----
// 32 rows x 128 cols per block, 128 threads, 4x8 register tile (f32x2 packed).
__global__ __launch_bounds__(128, 4) void k1_selfnbr(
        const float* __restrict__ atom, const float* __restrict__ W,
        const float* __restrict__ b) {
    __shared__ __align__(16) float sW[64 * 128];
    __shared__ __align__(16) float sA[64 * 36];
    const int tid = threadIdx.x;
    const int n0  = blockIdx.x * 32;

    for (int i = tid; i < 32 * 64; i += 128) {
        int r = i >> 6, k = i & 63;
        sA[k * 36 + r] = atom[(n0 + r) * 64 + k];
    }
    const int rg = tid >> 4, cg = tid & 15;
    const int r0 = rg * 4,  c0 = cg * 8;

    for (int half = 0; half < 2; ++half) {
        __syncthreads();
        for (int i = tid; i < 64 * 128; i += 128) {
            int c = i >> 6, k = i & 63;
            sW[k * 128 + c] = W[c * KW + half * 64 + k];
        }
        __syncthreads();

        u64 acc[4][4];
        #pragma unroll
        for (int r = 0; r < 4; r++)
            #pragma unroll
            for (int cp = 0; cp < 4; cp++)
                acc[r][cp] = (half == 0) ? pack2(b[c0 + 2*cp], b[c0 + 2*cp + 1])
                                         : 0ULL;

        #pragma unroll 8
        for (int k = 0; k < 64; ++k) {
            float4 av = *(const float4*)&sA[k * 36 + r0];
            ulonglong2 w0 = *(const ulonglong2*)&sW[k * 128 + c0];
            ulonglong2 w1 = *(const ulonglong2*)&sW[k * 128 + c0 + 4];
            u64 ad[4] = {dup2(av.x), dup2(av.y), dup2(av.z), dup2(av.w)};
            u64 wp[4] = {w0.x, w0.y, w1.x, w1.y};
            #pragma unroll
            for (int r = 0; r < 4; r++)
                #pragma unroll
                for (int cp = 0; cp < 4; cp++)
                    acc[r][cp] = ffma2(ad[r], wp[cp], acc[r][cp]);
        }

        float* dst = (half == 0) ? g_S : g_P;
        #pragma unroll
        for (int r = 0; r < 4; r++) {
            int n = n0 + r0 + r;
            ulonglong2 q0, q1;
            q0.x = acc[r][0]; q0.y = acc[r][1];
            q1.x = acc[r][2]; q1.y = acc[r][3];
            *(ulonglong2*)&dst[n * C_DIM + c0]     = q0;
            *(ulonglong2*)&dst[n * C_DIM + c0 + 4] = q1;
        }
    }
}

// ---------------- K2: Z[p,c] = S[n,c] + P[idx[p],c] + W_edge·nbr[p] + stats1
__global__ __launch_bounds__(128, 4) void k2_edge(
        const float* __restrict__ nbr, const int* __restrict__ idx,
        const float* __restrict__ W) {
    __shared__ __align__(16) float sW[64 * 128];
    __shared__ __align__(16) float sE[64 * 36];
    __shared__ float sSum[128], sSq[128];
    const int tid = threadIdx.x;
    if (tid < 128) { sSum[tid] = 0.f; sSq[tid] = 0.f; }
    for (int i = tid; i < 64 * 128; i += 128) {
        int c = i >> 6, k = i & 63;
        sW[k * 128 + c] = W[c * KW + 128 + k];
    }
    const int rg = tid >> 4, cg = tid & 15;
    const int r0 = rg * 4,  c0 = cg * 8;

    u64 lsum[4], lsq[4];
    #pragma unroll
    for (int cp = 0; cp < 4; cp++) { lsum[cp] = 0ULL; lsq[cp] = 0ULL; }

    const int ntiles = P_ROWS / 32;  // 37500
    for (int tile = blockIdx.x; tile < ntiles; tile += gridDim.x) {
        const int p0 = tile * 32;
        __syncthreads();
        for (int i = tid; i < 32 * 64; i += 128) {
            int r = i >> 6, k = i & 63;
            sE[k * 36 + r] = nbr[(size_t)(p0 + r) * 64 + k];
        }
        __syncthreads();

        u64 acc[4][4];
        #pragma unroll
        for (int r = 0; r < 4; r++)
            #pragma unroll
            for (int cp = 0; cp < 4; cp++) acc[r][cp] = 0ULL;

        #pragma unroll 8
        for (int k = 0; k < 64; ++k) {
            float4 av = *(const float4*)&sE[k * 36 + r0];
            ulonglong2 w0 = *(const ulonglong2*)&sW[k * 128 + c0];
            ulonglong2 w1 = *(const ulonglong2*)&sW[k * 128 + c0 + 4];
            u64 ad[4] = {dup2(av.x), dup2(av.y), dup2(av.z), dup2(av.w)};
            u64 wp[4] = {w0.x, w0.y, w1.x, w1.y};
            #pragma unroll
            for (int r = 0; r < 4; r++)
                #pragma unroll
                for (int cp = 0; cp < 4; cp++)
                    acc[r][cp] = ffma2(ad[r], wp[cp], acc[r][cp]);
        }

        #pragma unroll
        for (int r = 0; r < 4; r++) {
            const int p = p0 + r0 + r;
            const int n = p / 12;
            const int j = __ldg(&idx[p]);
            ulonglong2 s0 = *(const ulonglong2*)&g_S[n * C_DIM + c0];
            ulonglong2 s1 = *(const ulonglong2*)&g_S[n * C_DIM + c0 + 4];
            ulonglong2 p0v = *(const ulonglong2*)&g_P[j * C_DIM + c0];
            ulonglong2 p1v = *(const ulonglong2*)&g_P[j * C_DIM + c0 + 4];
            u64 z[4];
            z[0] = add2(acc[r][0], add2(s0.x, p0v.x));
            z[1] = add2(acc[r][1], add2(s0.y, p0v.y));
            z[2] = add2(acc[r][2], add2(s1.x, p1v.x));
            z[3] = add2(acc[r][3], add2(s1.y, p1v.y));
            #pragma unroll
            for (int cp = 0; cp < 4; cp++) {
                lsum[cp] = add2(lsum[cp], z[cp]);
                lsq[cp]  = ffma2(z[cp], z[cp], lsq[cp]);
            }
            ulonglong2 q0, q1;
            q0.x = z[0]; q0.y = z[1];
            q1.x = z[2]; q1.y = z[3];
            __stcs((ulonglong2*)&g_Z[(size_t)p * C_DIM + c0],     q0);
            __stcs((ulonglong2*)&g_Z[(size_t)p * C_DIM + c0 + 4], q1);
        }
    }

    #pragma unroll
    for (int cp = 0; cp < 4; cp++) {
        float slo, shi, qlo, qhi;
        unpack2(lsum[cp], slo, shi);
        unpack2(lsq[cp],  qlo, qhi);
        atomicAdd(&sSum[c0 + 2*cp],     slo);
        atomicAdd(&sSum[c0 + 2*cp + 1], shi);
        atomicAdd(&sSq[c0 + 2*cp],      qlo);
        atomicAdd(&sSq[c0 + 2*cp + 1],  qhi);
    }
    __syncthreads();
    if (tid < 128) {
        atomicAdd(&g_stats1[tid],        sSum[tid]);
        atomicAdd(&g_stats1[128 + tid],  sSq[tid]);
    }
}

// ---------------- K3: BN1 affine coefficients ----------------
__global__ void k3_aff1(const float* __restrict__ gamma1,
                        const float* __restrict__ beta1) {
    int c = threadIdx.x;  // 128
    float inv  = 1.f / (float)P_ROWS;
    float mean = g_stats1[c] * inv;
    float var  = g_stats1[128 + c] * inv - mean * mean;
    float sc   = gamma1[c] * rsqrtf(var + BN_EPS);
    g_aff1[c]        = sc;
    g_aff1[128 + c]  = beta1[c] - mean * sc;
}

// ---------------- K4: BN1 apply + gate + sum over M + stats2 ----------------
__global__ __launch_bounds__(256) void k4_reduce(const float* __restrict__ bw) {
    __shared__ float sSum[64], sSq[64];
    const int tid = threadIdx.x;
    if (tid < 64) { sSum[tid] = 0.f; sSq[tid] = 0.f; }
    __syncthreads();
    const int f  = tid & 63;
    const int al = tid >> 6;  // 0..3
    const float sc1 = g_aff1[f],      sh1 = g_aff1[128 + f];
    const float sc2 = g_aff1[64 + f], sh2 = g_aff1[192 + f];
    float lsum = 0.f, lsq = 0.f;

    for (int n = blockIdx.x * 4 + al; n < N_ATOMS; n += gridDim.x * 4) {
        float acc = 0.f;
        #pragma unroll
        for (int m = 0; m < 12; m++) {
            size_t base = (size_t)(n * 12 + m) * C_DIM;
            float z1 = fmaf(__ldcs(&g_Z[base + f]),      sc1, sh1);
            float z2 = fmaf(__ldcs(&g_Z[base + 64 + f]), sc2, sh2);
            float w  = __ldg(&bw[n * 12 + m]);
            float sig = __fdividef(1.f, 1.f + __expf(-z1));
            float sp  = softplus_fast(z2);
            acc = fmaf(w * w * sig, sp, acc);
        }
        g_NS[n * 64 + f] = acc;
        lsum += acc;
        lsq  = fmaf(acc, acc, lsq);
    }
    atomicAdd(&sSum[f], lsum);
    atomicAdd(&sSq[f],  lsq);
    __syncthreads();
    if (tid < 64) {
        atomicAdd(&g_stats2[tid],      sSum[tid]);
        atomicAdd(&g_stats2[64 + tid], sSq[tid]);
    }
}

// ---------------- K5: BN2 affine coefficients ----------------
__global__ void k5_aff2(const float* __restrict__ gamma2,
                        const float* __restrict__ beta2) {
    int f = threadIdx.x;  // 64
    float inv  = 1.f / (float)N_ATOMS;
    float mean = g_stats2[f] * inv;
    float var  = g_stats2[64 + f] * inv - mean * mean;
    float sc   = gamma2[f] * rsqrtf(var + BN_EPS);
    g_aff2[f]       = sc;
    g_aff2[64 + f]  = beta2[f] - mean * sc;
}

// ---------------- K6: out = softplus(atom + BN2(NS)) ----------------
__global__ void k6_out(const float* __restrict__ atom, float* __restrict__ out) {
    int i = blockIdx.x * blockDim.x + threadIdx.x;
    if (i < N_ATOMS * F_DIM) {
        int f = i & 63;
        float x = atom[i] + fmaf(g_NS[i], g_aff2[f], g_aff2[64 + f]);
        out[i] = softplus_fast(x);
    }
}

// ---------------- launch ----------------
extern "C" void kernel_launch(void* const* d_in, const int* in_sizes, int n_in,
                              void* d_out, int out_size) {
    const float* atom   = (const float*)d_in[0];
    const float* nbr    = (const float*)d_in[1];
    const float* bw     = (const float*)d_in[2];
    const int*   idx    = (const int*)  d_in[3];
    const float* W      = (const float*)d_in[4];
    const float* b      = (const float*)d_in[5];
    const float* gamma1 = (const float*)d_in[6];
    const float* beta1  = (const float*)d_in[7];
    const float* gamma2 = (const float*)d_in[8];
    const float* beta2  = (const float*)d_in[9];
    float* out = (float*)d_out;

    k0_zero<<<1, 256>>>();
    k1_selfnbr<<<N_ATOMS / 32, 128>>>(atom, W, b);
    k2_edge<<<592, 128>>>(nbr, idx, W);
    k3_aff1<<<1, 128>>>(gamma1, beta1);
    k4_reduce<<<592, 256>>>(bw);
    k5_aff2<<<1, 64>>>(gamma2, beta2);
    k6_out<<<(N_ATOMS * F_DIM + 255) / 256, 256>>>(atom, out);
}